// round 3
// baseline (speedup 1.0000x reference)
#include <cuda_runtime.h>
#include <math.h>
#include <stdint.h>

#define D_MODEL 768
#define HEADS   12
#define GROUPS  2
#define DK      64
#define KVD     128
#define BSZ     4
#define SEQ     2048
#define MTOT    (BSZ*SEQ)

typedef unsigned long long ull;

// ---------------- packed fp32x2 helpers (Blackwell dual-FP32 pipe) -------------
__device__ __forceinline__ ull pack2(float x, float y) {
    ull r; asm("mov.b64 %0, {%1, %2};" : "=l"(r) : "f"(x), "f"(y)); return r;
}
__device__ __forceinline__ void ffma2(ull& d, ull a, ull b) {
    asm("fma.rn.f32x2 %0, %1, %2, %0;" : "+l"(d) : "l"(a), "l"(b));
}
__device__ __forceinline__ void fmul2(ull& d, ull a) {
    asm("mul.rn.f32x2 %0, %0, %1;" : "+l"(d) : "l"(a));
}
__device__ __forceinline__ float2 u2f(ull v) {
    float2 r; asm("mov.b64 {%0, %1}, %2;" : "=f"(r.x), "=f"(r.y) : "l"(v)); return r;
}

// ---------------- scratch (static device globals: no allocation) ----------------
__device__ float g_qp[(size_t)BSZ*HEADS*SEQ*DK];   // [b][h][s][d]
__device__ float g_kp[(size_t)BSZ*GROUPS*SEQ*DK];  // [b][g][s][d]
__device__ float g_vt[(size_t)BSZ*GROUPS*DK*SEQ];  // [b][g][d][s]  (TRANSPOSED)
__device__ float g_ao[(size_t)BSZ*SEQ*D_MODEL];    // [b][s][h*64+d]

// ---------------- GEMM: C = A[M,K] @ B[K,N] + bias --------------------------------
// 128x128 tile, K-step 8, double-buffered smem, 8x8 per thread via fp32x2.
// MODE 0: row-major C[M,N].
// MODE 1: head-split C[((b*H+head)*SEQ+s)*64+d].
// MODE 2: z==0 -> head-split (K proj); z==1 -> transposed V: C[((b*G+g)*64+d)*SEQ+s].
template<int MODE>
__global__ void __launch_bounds__(256, 2) gemm_k(
    const float* __restrict__ A0, const float* __restrict__ B0,
    const float* __restrict__ bias0, float* __restrict__ C0,
    const float* __restrict__ A1, const float* __restrict__ B1,
    const float* __restrict__ bias1, float* __restrict__ C1,
    int N, int K)
{
    const float* A = A0; const float* B = B0; const float* bias = bias0; float* C = C0;
    if (blockIdx.z) { A = A1; B = B1; bias = bias1; C = C1; }

    __shared__ float As[2][8][128];   // [buf][k][m]
    __shared__ float Bs[2][8][128];   // [buf][k][n]

    const int t    = threadIdx.x;
    const int row0 = blockIdx.y * 128;
    const int n0   = blockIdx.x * 128;
    const int tr   = t >> 4, tc = t & 15;
    const int ar   = t >> 1, ak = (t & 1) << 2;
    const int bk   = t >> 5, bc = (t & 31) << 2;

    ull acc[8][4];
#pragma unroll
    for (int i = 0; i < 8; i++)
#pragma unroll
        for (int j = 0; j < 4; j++) acc[i][j] = 0ull;

    float4 av = *(const float4*)(A + (size_t)(row0 + ar) * K + ak);
    float4 bv = *(const float4*)(B + (size_t)bk * N + n0 + bc);
    As[0][ak + 0][ar] = av.x; As[0][ak + 1][ar] = av.y;
    As[0][ak + 2][ar] = av.z; As[0][ak + 3][ar] = av.w;
    *(float4*)(&Bs[0][bk][bc]) = bv;
    __syncthreads();

    int buf = 0;
    for (int k0 = 0; k0 < K; k0 += 8) {
        float4 anx, bnx;
        const bool more = (k0 + 8) < K;
        if (more) {
            anx = *(const float4*)(A + (size_t)(row0 + ar) * K + k0 + 8 + ak);
            bnx = *(const float4*)(B + (size_t)(k0 + 8 + bk) * N + n0 + bc);
        }
#pragma unroll
        for (int kk = 0; kk < 8; kk++) {
            const float4 a0 = *(const float4*)(&As[buf][kk][tr * 8]);
            const float4 a1 = *(const float4*)(&As[buf][kk][tr * 8 + 4]);
            const ulonglong2 bA = *(const ulonglong2*)(&Bs[buf][kk][tc * 4]);
            const ulonglong2 bB = *(const ulonglong2*)(&Bs[buf][kk][64 + tc * 4]);
            ull a2[8];
            a2[0] = pack2(a0.x, a0.x); a2[1] = pack2(a0.y, a0.y);
            a2[2] = pack2(a0.z, a0.z); a2[3] = pack2(a0.w, a0.w);
            a2[4] = pack2(a1.x, a1.x); a2[5] = pack2(a1.y, a1.y);
            a2[6] = pack2(a1.z, a1.z); a2[7] = pack2(a1.w, a1.w);
#pragma unroll
            for (int i = 0; i < 8; i++) {
                ffma2(acc[i][0], a2[i], bA.x);
                ffma2(acc[i][1], a2[i], bA.y);
                ffma2(acc[i][2], a2[i], bB.x);
                ffma2(acc[i][3], a2[i], bB.y);
            }
        }
        if (more) {
            const int nb = buf ^ 1;
            As[nb][ak + 0][ar] = anx.x; As[nb][ak + 1][ar] = anx.y;
            As[nb][ak + 2][ar] = anx.z; As[nb][ak + 3][ar] = anx.w;
            *(float4*)(&Bs[nb][bk][bc]) = bnx;
        }
        __syncthreads();
        buf ^= 1;
    }

    const float4 biA = *(const float4*)(bias + n0 + tc * 4);
    const float4 biB = *(const float4*)(bias + n0 + 64 + tc * 4);
#pragma unroll
    for (int i = 0; i < 8; i++) {
        const int m = row0 + tr * 8 + i;
        const float2 p0 = u2f(acc[i][0]), p1 = u2f(acc[i][1]);
        const float2 p2 = u2f(acc[i][2]), p3 = u2f(acc[i][3]);
        float4 oA = make_float4(p0.x + biA.x, p0.y + biA.y, p1.x + biA.z, p1.y + biA.w);
        float4 oB = make_float4(p2.x + biB.x, p2.y + biB.y, p3.x + biB.z, p3.y + biB.w);
        if (MODE == 0) {
            float* dst = C + (size_t)m * N + n0;
            *(float4*)(dst + tc * 4)      = oA;
            *(float4*)(dst + 64 + tc * 4) = oB;
        } else if (MODE == 1 || (MODE == 2 && blockIdx.z == 0)) {
            const int bi = m >> 11, s = m & 2047;
            const int H = N >> 6;
            const int headA = n0 >> 6, headB = headA + 1;
            float* dA = C + ((((size_t)(bi * H + headA)) * SEQ + s) << 6) + tc * 4;
            float* dB = C + ((((size_t)(bi * H + headB)) * SEQ + s) << 6) + tc * 4;
            *(float4*)dA = oA;
            *(float4*)dB = oB;
        } else {
            // MODE 2, z==1: transposed V  ->  C[((b*G+g)*64 + d)*SEQ + s]
            const int bi = m >> 11, s = m & 2047;
            const float a4[4] = {oA.x, oA.y, oA.z, oA.w};
            const float b4[4] = {oB.x, oB.y, oB.z, oB.w};
#pragma unroll
            for (int j = 0; j < 4; j++) {
                const int d = tc * 4 + j;
                C[((size_t)(bi * GROUPS + 0) * DK + d) * SEQ + s] = a4[j];
                C[((size_t)(bi * GROUPS + 1) * DK + d) * SEQ + s] = b4[j];
            }
        }
    }
}

// ---------------- Flash attention, fp32x2, Br=128 / Bc=64 ------------------------
// 256 threads, 8 rows x 4 cols per thread.
// S phase: packed over d (Q,K adjacent in smem, zero repacks), 2 jj-passes.
// PV phase: packed over the REDUCTION dim j (P adjacent in Ss rows, V adjacent in
//           transposed Vt rows) -> zero pack movs; horizontal add at the very end.
#define FL_SMEM_FLOATS (128*68 + 64*68 + 64*68 + 128*68 + 3*128)
#define FL_SMEM_BYTES  (FL_SMEM_FLOATS * 4)

__global__ void __launch_bounds__(256, 2) flash_k(
    const float* __restrict__ qp, const float* __restrict__ kp,
    const float* __restrict__ vt, float* __restrict__ ao)
{
    extern __shared__ float sm[];
    float* Qs   = sm;                 // [128][68]  q rows
    float* Ks   = Qs + 128 * 68;      // [64][68]   kv rows (s-major)
    float* Vs   = Ks + 64 * 68;       // [64][68]   V TRANSPOSED: [d][j]
    float* Ss   = Vs + 64 * 68;       // [128][68]  scores/P
    float* mrow = Ss + 128 * 68;
    float* lrow = mrow + 128;
    float* crow = lrow + 128;

    const int t  = threadIdx.x;
    const int qt = blockIdx.x, h = blockIdx.y, b = blockIdx.z;
    const int g  = h & 1;
    const float* qbase  = qp + (((size_t)(b * HEADS + h)) * SEQ + (size_t)qt * 128) * DK;
    const float* kbase  = kp + (((size_t)(b * GROUPS + g)) * SEQ) * DK;
    const float* vtbase = vt + ((size_t)(b * GROUPS + g)) * DK * SEQ;

    // load Q tile [128][64]
#pragma unroll
    for (int i = 0; i < 8; i++) {
        int f = t + 256 * i;
        int r = f >> 4, d4 = (f & 15) << 2;
        *(float4*)(Qs + r * 68 + d4) = *(const float4*)(qbase + r * 64 + d4);
    }
    if (t < 128) { mrow[t] = -1e30f; lrow[t] = 0.f; }

    const int tr = t >> 4, tc = t & 15;
    ull oacc[8][4];   // packed over j; output dim of oacc[i][dd] is tc + 16*dd
#pragma unroll
    for (int i = 0; i < 8; i++)
#pragma unroll
        for (int dd = 0; dd < 4; dd++) oacc[i][dd] = 0ull;

    for (int kt = 0; kt < SEQ / 64; kt++) {
        __syncthreads();
        // load K [s][d] rows and Vt [d][j] rows (both coalesced, conflict-free STS)
#pragma unroll
        for (int i = 0; i < 4; i++) {
            int f = t + 256 * i;
            int r = f >> 4, c4 = (f & 15) << 2;
            *(float4*)(Ks + r * 68 + c4) = *(const float4*)(kbase + (size_t)(kt * 64 + r) * 64 + c4);
            *(float4*)(Vs + r * 68 + c4) = *(const float4*)(vtbase + (size_t)r * SEQ + kt * 64 + c4);
        }
        __syncthreads();

        // ---- S = Q @ K^T, packed over d, two jj-passes (cols tc+16*jj)
#pragma unroll
        for (int half = 0; half < 2; half++) {
            const int c0 = tc + 16 * (2 * half);
            const int c1 = tc + 16 * (2 * half + 1);
            ull s2[8][2];
#pragma unroll
            for (int i = 0; i < 8; i++) { s2[i][0] = 0ull; s2[i][1] = 0ull; }
#pragma unroll 4
            for (int d = 0; d < 64; d += 4) {
                const ulonglong2 b0 = *(const ulonglong2*)(Ks + c0 * 68 + d);
                const ulonglong2 b1 = *(const ulonglong2*)(Ks + c1 * 68 + d);
#pragma unroll
                for (int i = 0; i < 8; i++) {
                    const ulonglong2 a = *(const ulonglong2*)(Qs + (tr * 8 + i) * 68 + d);
                    ffma2(s2[i][0], a.x, b0.x);
                    ffma2(s2[i][0], a.y, b0.y);
                    ffma2(s2[i][1], a.x, b1.x);
                    ffma2(s2[i][1], a.y, b1.y);
                }
            }
#pragma unroll
            for (int i = 0; i < 8; i++) {
                const float2 f0 = u2f(s2[i][0]), f1 = u2f(s2[i][1]);
                Ss[(tr * 8 + i) * 68 + c0] = f0.x + f0.y;
                Ss[(tr * 8 + i) * 68 + c1] = f1.x + f1.y;
            }
        }
        __syncthreads();

        // ---- online softmax: 2 threads per row, float4-vectorized smem traffic
        {
            const int r = t >> 1, half = t & 1;
            float* srow = Ss + r * 68 + half * 32;
            float mloc = -1e30f;
#pragma unroll
            for (int j4 = 0; j4 < 32; j4 += 4) {
                const float4 w = *(const float4*)(srow + j4);
                mloc = fmaxf(mloc, fmaxf(fmaxf(w.x, w.y), fmaxf(w.z, w.w)));
            }
            mloc = fmaxf(mloc, __shfl_xor_sync(0xffffffffu, mloc, 1));
            const float mold = mrow[r];
            const float mnew = fmaxf(mold, mloc);
            const float corr = __expf(mold - mnew);
            float ssum = 0.f;
#pragma unroll
            for (int j4 = 0; j4 < 32; j4 += 4) {
                float4 w = *(const float4*)(srow + j4);
                w.x = __expf(w.x - mnew); w.y = __expf(w.y - mnew);
                w.z = __expf(w.z - mnew); w.w = __expf(w.w - mnew);
                *(float4*)(srow + j4) = w;
                ssum += (w.x + w.y) + (w.z + w.w);
            }
            ssum += __shfl_xor_sync(0xffffffffu, ssum, 1);
            if (!half) {
                mrow[r] = mnew;
                lrow[r] = lrow[r] * corr + ssum;
                crow[r] = corr;
            }
        }
        __syncthreads();

        // ---- O = O*corr + P @ V, packed over j (NO pack movs)
#pragma unroll
        for (int i = 0; i < 8; i++) {
            const float cf = crow[tr * 8 + i];
            const ull c2 = pack2(cf, cf);
            fmul2(oacc[i][0], c2); fmul2(oacc[i][1], c2);
            fmul2(oacc[i][2], c2); fmul2(oacc[i][3], c2);
        }
#pragma unroll 4
        for (int j4 = 0; j4 < 64; j4 += 4) {
            ulonglong2 v[4];
#pragma unroll
            for (int dd = 0; dd < 4; dd++)
                v[dd] = *(const ulonglong2*)(Vs + (tc + 16 * dd) * 68 + j4);
#pragma unroll
            for (int i = 0; i < 8; i++) {
                const ulonglong2 p = *(const ulonglong2*)(Ss + (tr * 8 + i) * 68 + j4);
#pragma unroll
                for (int dd = 0; dd < 4; dd++) {
                    ffma2(oacc[i][dd], p.x, v[dd].x);
                    ffma2(oacc[i][dd], p.y, v[dd].y);
                }
            }
        }
    }

    // ---- write out: ao[b][s][h*64 + d], d = tc + 16*dd (horizontal add here)
#pragma unroll
    for (int i = 0; i < 8; i++) {
        const int r = tr * 8 + i;
        const float linv = 1.f / lrow[r];
        float* dst = ao + ((size_t)(b * SEQ + qt * 128 + r)) * D_MODEL + h * DK;
#pragma unroll
        for (int dd = 0; dd < 4; dd++) {
            const float2 f2 = u2f(oacc[i][dd]);
            dst[tc + 16 * dd] = (f2.x + f2.y) * linv;
        }
    }
}

// ---------------- launch -----------------------------------------------------
extern "C" void kernel_launch(void* const* d_in, const int* in_sizes, int n_in,
                              void* d_out, int out_size)
{
    const float* q  = (const float*)d_in[0];
    const float* k  = (const float*)d_in[1];
    const float* v  = (const float*)d_in[2];
    const float* Wq = (const float*)d_in[3];
    const float* bq = (const float*)d_in[4];
    const float* Wk = (const float*)d_in[5];
    const float* bk = (const float*)d_in[6];
    const float* Wv = (const float*)d_in[7];
    const float* bv = (const float*)d_in[8];
    const float* Wo = (const float*)d_in[9];
    const float* bo = (const float*)d_in[10];
    float* out = (float*)d_out;

    float *qp, *kp, *vt, *ao;
    cudaGetSymbolAddress((void**)&qp, g_qp);
    cudaGetSymbolAddress((void**)&kp, g_kp);
    cudaGetSymbolAddress((void**)&vt, g_vt);
    cudaGetSymbolAddress((void**)&ao, g_ao);

    // 1) Q projection -> head-major qp
    gemm_k<1><<<dim3(D_MODEL / 128, MTOT / 128, 1), 256>>>(
        q, Wq, bq, qp, q, Wq, bq, qp, D_MODEL, D_MODEL);

    // 2) K (head-split) and V (transposed) projections in one launch
    gemm_k<2><<<dim3(KVD / 128, MTOT / 128, 2), 256>>>(
        k, Wk, bk, kp, v, Wv, bv, vt, KVD, D_MODEL);

    // 3) flash attention -> ao [b][s][768]
    cudaFuncSetAttribute(flash_k, cudaFuncAttributeMaxDynamicSharedMemorySize, FL_SMEM_BYTES);
    flash_k<<<dim3(SEQ / 128, HEADS, BSZ), 256, FL_SMEM_BYTES>>>(qp, kp, vt, ao);

    // 4) output projection -> d_out
    gemm_k<0><<<dim3(D_MODEL / 128, MTOT / 128, 1), 256>>>(
        ao, Wo, bo, out, ao, Wo, bo, out, D_MODEL, D_MODEL);
}